// round 4
// baseline (speedup 1.0000x reference)
#include <cuda_runtime.h>
#include <cuda_bf16.h>

// Sorted segment-sum: values (N, 256) fp32, segment_ids (N) sorted int32 in [0, B),
// out (B, 256) fp32.  Persistent single-wave streaming kernel; register
// accumulation with rare vectorized-REDG flushes at segment boundaries.

#define C_COLS   256
#define CV       64      // float4 per row
#define UNR      8       // independent row-loads per thread per iteration (MLP)
#define GRID     608     // 4 CTAs/SM x 152 SMs (GB300) -> single wave
#define GRAN     32      // rows per inner iteration (4 y-streams x UNR)

__global__ void zero_out_kernel(float* __restrict__ out, int nelem) {
    int i = blockIdx.x * blockDim.x + threadIdx.x;
    if (i < nelem) out[i] = 0.0f;
}

// Vectorized fire-and-forget global reduction: one REDG.128.
__device__ __forceinline__ void red_add_v4(float* addr, float4 v) {
    asm volatile("red.global.add.v4.f32 [%0], {%1, %2, %3, %4};"
                 :: "l"(addr), "f"(v.x), "f"(v.y), "f"(v.z), "f"(v.w)
                 : "memory");
}

__global__ __launch_bounds__(256, 4)
void segsum_kernel(const float4* __restrict__ vals,
                   const int*    __restrict__ seg,
                   float*        __restrict__ out,
                   int n, int rows_per_block)
{
    const int col = threadIdx.x;   // 0..63  (float4 column group)
    const int y   = threadIdx.y;   // 0..3   (row sub-stream)

    int r0 = blockIdx.x * rows_per_block;
    if (r0 >= n) return;
    int r1 = r0 + rows_per_block;
    if (r1 > n) r1 = n;

    const int full_end = r0 + ((r1 - r0) / GRAN) * GRAN;

    float4 acc = make_float4(0.f, 0.f, 0.f, 0.f);
    int cur = (r0 + y < r1) ? __ldg(&seg[r0 + y]) : -1;

    #pragma unroll 1
    for (int r = r0; r < full_end; r += GRAN) {
        float4 buf[UNR];
        int    sb[UNR];
        #pragma unroll
        for (int u = 0; u < UNR; u++)
            buf[u] = __ldcs(&vals[(size_t)(r + y + 4 * u) * CV + col]);
        #pragma unroll
        for (int u = 0; u < UNR; u++)
            sb[u] = __ldg(&seg[r + y + 4 * u]);

        #pragma unroll
        for (int u = 0; u < UNR; u++) {
            if (sb[u] != cur) {
                red_add_v4(out + (size_t)cur * C_COLS + col * 4, acc);
                acc = make_float4(0.f, 0.f, 0.f, 0.f);
                cur = sb[u];
            }
            acc.x += buf[u].x;
            acc.y += buf[u].y;
            acc.z += buf[u].z;
            acc.w += buf[u].w;
        }
    }

    // remainder rows (span not a multiple of GRAN, or n ragged)
    for (int row = full_end + y; row < r1; row += 4) {
        float4 v = __ldcs(&vals[(size_t)row * CV + col]);
        const int s = __ldg(&seg[row]);
        if (s != cur) {
            red_add_v4(out + (size_t)cur * C_COLS + col * 4, acc);
            acc = make_float4(0.f, 0.f, 0.f, 0.f);
            cur = s;
        }
        acc.x += v.x;
        acc.y += v.y;
        acc.z += v.z;
        acc.w += v.w;
    }

    if (cur >= 0)
        red_add_v4(out + (size_t)cur * C_COLS + col * 4, acc);
}

extern "C" void kernel_launch(void* const* d_in, const int* in_sizes, int n_in,
                              void* d_out, int out_size)
{
    const float* values = (const float*)d_in[0];
    const int*   segids = (const int*)d_in[1];
    float* out = (float*)d_out;

    const int n = in_sizes[1];   // number of rows

    // Output is poisoned; zero it first (flushes accumulate on top).
    {
        int threads = 256;
        int blocks = (out_size + threads - 1) / threads;
        zero_out_kernel<<<blocks, threads>>>(out, out_size);
    }

    // Contiguous span per block, rounded up to GRAN rows, single wave.
    int granules = (n + GRAN - 1) / GRAN;
    int gran_per_block = (granules + GRID - 1) / GRID;
    int rows_per_block = gran_per_block * GRAN;
    int grid = (n + rows_per_block - 1) / rows_per_block;

    dim3 block(64, 4);
    segsum_kernel<<<grid, block>>>((const float4*)values, segids, out,
                                   n, rows_per_block);
}

// round 5
// speedup vs baseline: 1.0167x; 1.0167x over previous
#include <cuda_runtime.h>
#include <cuda_bf16.h>

// Sorted segment-sum: values (N, 256) fp32, segment_ids (N) sorted int32 in [0, B),
// out (B, 256) fp32.  Streaming HBM-bound kernel: many small blocks (self-
// balancing waves), register accumulation, rare vectorized-REDG flushes.

#define C_COLS   256
#define CV       64      // float4 per row (256 floats)
#define RPB      256     // rows per block (256 divides N exactly -> no ragged tail)
#define UNR      8       // independent row-loads per thread per iteration (MLP)

// Vectorized fire-and-forget global reduction: one REDG.128.
__device__ __forceinline__ void red_add_v4(float* addr, float4 v) {
    asm volatile("red.global.add.v4.f32 [%0], {%1, %2, %3, %4};"
                 :: "l"(addr), "f"(v.x), "f"(v.y), "f"(v.z), "f"(v.w)
                 : "memory");
}

__global__ __launch_bounds__(256)
void segsum_kernel(const float4* __restrict__ vals,
                   const int*    __restrict__ seg,
                   float*        __restrict__ out,
                   int n)
{
    const int col = threadIdx.x;   // 0..63  (float4 column group)
    const int y   = threadIdx.y;   // 0..3   (row sub-stream)

    const int row0 = blockIdx.x * RPB;
    int rows = n - row0;
    if (rows > RPB) rows = RPB;

    float4 acc = make_float4(0.f, 0.f, 0.f, 0.f);
    int cur = (y < rows) ? __ldg(&seg[row0 + y]) : -1;

    if (rows == RPB) {
        // fast path: full block, 8 iterations of 8-way front-batched loads
        #pragma unroll 1
        for (int r = y; r < RPB; r += 4 * UNR) {
            float4 buf[UNR];
            int    sb[UNR];
            #pragma unroll
            for (int u = 0; u < UNR; u++)
                buf[u] = __ldcs(&vals[(size_t)(row0 + r + 4 * u) * CV + col]);
            #pragma unroll
            for (int u = 0; u < UNR; u++)
                sb[u] = __ldg(&seg[row0 + r + 4 * u]);

            #pragma unroll
            for (int u = 0; u < UNR; u++) {
                if (sb[u] != cur) {
                    red_add_v4(out + (size_t)cur * C_COLS + col * 4, acc);
                    acc = make_float4(0.f, 0.f, 0.f, 0.f);
                    cur = sb[u];
                }
                acc.x += buf[u].x;
                acc.y += buf[u].y;
                acc.z += buf[u].z;
                acc.w += buf[u].w;
            }
        }
    } else {
        // ragged tail block
        for (int r = y; r < rows; r += 4) {
            float4 v = __ldcs(&vals[(size_t)(row0 + r) * CV + col]);
            const int s = __ldg(&seg[row0 + r]);
            if (s != cur) {
                red_add_v4(out + (size_t)cur * C_COLS + col * 4, acc);
                acc = make_float4(0.f, 0.f, 0.f, 0.f);
                cur = s;
            }
            acc.x += v.x;
            acc.y += v.y;
            acc.z += v.z;
            acc.w += v.w;
        }
    }

    if (cur >= 0)
        red_add_v4(out + (size_t)cur * C_COLS + col * 4, acc);
}

extern "C" void kernel_launch(void* const* d_in, const int* in_sizes, int n_in,
                              void* d_out, int out_size)
{
    const float* values = (const float*)d_in[0];
    const int*   segids = (const int*)d_in[1];
    float* out = (float*)d_out;

    const int n = in_sizes[1];   // number of rows

    // Output is poisoned; zero it (graph-capturable memset node), flushes
    // accumulate on top.
    cudaMemsetAsync(out, 0, (size_t)out_size * sizeof(float));

    dim3 block(64, 4);
    int grid = (n + RPB - 1) / RPB;
    segsum_kernel<<<grid, block>>>((const float4*)values, segids, out, n);
}

// round 6
// speedup vs baseline: 1.0262x; 1.0094x over previous
#include <cuda_runtime.h>
#include <cuda_bf16.h>

// Sorted segment-sum: values (N, 256) fp32, segment_ids (N) sorted int32 in [0, B),
// out (B, 256) fp32.  Streaming HBM-bound kernel: many small self-balancing
// blocks, register accumulation, rare vectorized-REDG flushes. Blocks that lie
// entirely inside one segment (~87% at avg seglen 2048) take a stripped
// pure-streaming path with no per-row segment checks.

#define C_COLS   256
#define CV       64      // float4 per row (256 floats)
#define RPB      256     // rows per block (divides N exactly -> no ragged tail)
#define UNR      8       // independent row-loads per thread per iteration (MLP)

// Vectorized fire-and-forget global reduction: one REDG.128.
__device__ __forceinline__ void red_add_v4(float* addr, float4 v) {
    asm volatile("red.global.add.v4.f32 [%0], {%1, %2, %3, %4};"
                 :: "l"(addr), "f"(v.x), "f"(v.y), "f"(v.z), "f"(v.w)
                 : "memory");
}

__global__ __launch_bounds__(256)
void segsum_kernel(const float4* __restrict__ vals,
                   const int*    __restrict__ seg,
                   float*        __restrict__ out,
                   int n)
{
    const int col = threadIdx.x;   // 0..63  (float4 column group)
    const int y   = threadIdx.y;   // 0..3   (row sub-stream)

    const int row0 = blockIdx.x * RPB;
    int rows = n - row0;
    if (rows > RPB) rows = RPB;

    float4 acc = make_float4(0.f, 0.f, 0.f, 0.f);

    if (rows == RPB) {
        const int s_first = __ldg(&seg[row0]);
        const int s_last  = __ldg(&seg[row0 + RPB - 1]);

        if (s_first == s_last) {
            // ---- uniform-segment fast path: pure streaming accumulate ----
            #pragma unroll 1
            for (int r = y; r < RPB; r += 4 * UNR) {
                float4 buf[UNR];
                #pragma unroll
                for (int u = 0; u < UNR; u++)
                    buf[u] = __ldcs(&vals[(size_t)(row0 + r + 4 * u) * CV + col]);
                #pragma unroll
                for (int u = 0; u < UNR; u++) {
                    acc.x += buf[u].x;
                    acc.y += buf[u].y;
                    acc.z += buf[u].z;
                    acc.w += buf[u].w;
                }
            }
            red_add_v4(out + (size_t)s_first * C_COLS + col * 4, acc);
            return;
        }

        // ---- boundary block: per-row segment tracking ----
        int cur = s_first;  // seg[row0 + y] may differ, but sorted => handled below
        cur = __ldg(&seg[row0 + y]);
        #pragma unroll 1
        for (int r = y; r < RPB; r += 4 * UNR) {
            int sb[UNR];
            #pragma unroll
            for (int u = 0; u < UNR; u++)
                sb[u] = __ldg(&seg[row0 + r + 4 * u]);
            float4 buf[UNR];
            #pragma unroll
            for (int u = 0; u < UNR; u++)
                buf[u] = __ldcs(&vals[(size_t)(row0 + r + 4 * u) * CV + col]);

            #pragma unroll
            for (int u = 0; u < UNR; u++) {
                if (sb[u] != cur) {
                    red_add_v4(out + (size_t)cur * C_COLS + col * 4, acc);
                    acc = make_float4(0.f, 0.f, 0.f, 0.f);
                    cur = sb[u];
                }
                acc.x += buf[u].x;
                acc.y += buf[u].y;
                acc.z += buf[u].z;
                acc.w += buf[u].w;
            }
        }
        red_add_v4(out + (size_t)cur * C_COLS + col * 4, acc);
        return;
    }

    // ---- ragged tail block (n not multiple of RPB) ----
    int cur = (y < rows) ? __ldg(&seg[row0 + y]) : -1;
    for (int r = y; r < rows; r += 4) {
        float4 v = __ldcs(&vals[(size_t)(row0 + r) * CV + col]);
        const int s = __ldg(&seg[row0 + r]);
        if (s != cur) {
            red_add_v4(out + (size_t)cur * C_COLS + col * 4, acc);
            acc = make_float4(0.f, 0.f, 0.f, 0.f);
            cur = s;
        }
        acc.x += v.x;
        acc.y += v.y;
        acc.z += v.z;
        acc.w += v.w;
    }
    if (cur >= 0)
        red_add_v4(out + (size_t)cur * C_COLS + col * 4, acc);
}

extern "C" void kernel_launch(void* const* d_in, const int* in_sizes, int n_in,
                              void* d_out, int out_size)
{
    const float* values = (const float*)d_in[0];
    const int*   segids = (const int*)d_in[1];
    float* out = (float*)d_out;

    const int n = in_sizes[1];   // number of rows

    // Output is poisoned; zero it (graph-capturable memset node), flushes
    // accumulate on top.
    cudaMemsetAsync(out, 0, (size_t)out_size * sizeof(float));

    dim3 block(64, 4);
    int grid = (n + RPB - 1) / RPB;
    segsum_kernel<<<grid, block>>>((const float4*)values, segids, out, n);
}